// round 4
// baseline (speedup 1.0000x reference)
#include <cuda_runtime.h>

#define N_NODES 100000
#define N_EDGES 1600000
#define F 64

// Scratch (device globals — no allocation allowed in kernel_launch)
__device__ float g_deg[N_NODES];
__device__ float g_dinv[N_NODES];
__device__ float g_xs[N_NODES * F];   // (x @ W) * dinv[row]

__global__ void k_deg_init() {
    int i = blockIdx.x * blockDim.x + threadIdx.x;
    if (i < N_NODES) g_deg[i] = 1.0f;   // self-loop contributes 1
}

// 4 edges per thread via int4 load of dst indices (N_EDGES % 4 == 0)
__global__ void k_deg_scatter(const int* __restrict__ ei) {
    int t = blockIdx.x * blockDim.x + threadIdx.x;
    if (t < N_EDGES / 4) {
        int4 d4 = ((const int4*)(ei + N_EDGES))[t];
        if ((unsigned)d4.x < N_NODES) atomicAdd(&g_deg[d4.x], 1.0f);
        if ((unsigned)d4.y < N_NODES) atomicAdd(&g_deg[d4.y], 1.0f);
        if ((unsigned)d4.z < N_NODES) atomicAdd(&g_deg[d4.z], 1.0f);
        if ((unsigned)d4.w < N_NODES) atomicAdd(&g_deg[d4.w], 1.0f);
    }
}

__global__ void k_dinv() {
    int i = blockIdx.x * blockDim.x + threadIdx.x;
    if (i < N_NODES) g_dinv[i] = rsqrtf(g_deg[i]);  // deg >= 1 always
}

// xw = x @ W ; xs = xw * dinv[row] ; out_init(self loop) = xs * dinv[row]
// 256 threads/block, 4 rows per block, thread (r = tid>>6, c = tid&63)
__global__ void k_gemm(const float* __restrict__ x,
                       const float* __restrict__ W,
                       float* __restrict__ out) {
    __shared__ float Ws[F * F];
    __shared__ float xsh[4 * F];
    int tid = threadIdx.x;
    #pragma unroll
    for (int i = tid; i < F * F; i += 256) Ws[i] = W[i];
    int row0 = blockIdx.x * 4;
    for (int i = tid; i < 4 * F; i += 256) {
        int r = row0 + (i >> 6);
        xsh[i] = (r < N_NODES) ? x[r * F + (i & 63)] : 0.0f;
    }
    __syncthreads();
    int r = tid >> 6;
    int c = tid & 63;
    int row = row0 + r;
    if (row < N_NODES) {
        float acc = 0.0f;
        #pragma unroll
        for (int k = 0; k < F; k++) acc += xsh[r * F + k] * Ws[k * F + c];
        float di = g_dinv[row];
        float xsv = acc * di;
        g_xs[row * F + c] = xsv;
        out[row * F + c] = xsv * di;   // self-loop message
    }
}

// 16 threads per edge, float4 gather + 4 scalar REDs per thread
__global__ void k_scatter(const int* __restrict__ ei,
                          float* __restrict__ out) {
    long long tid = (long long)blockIdx.x * blockDim.x + threadIdx.x;
    int e = (int)(tid >> 4);
    int part = (int)(tid & 15);
    if (e < N_EDGES) {
        unsigned src = (unsigned)__ldg(ei + e);
        unsigned dst = (unsigned)__ldg(ei + N_EDGES + e);
        if (src < N_NODES && dst < N_NODES) {
            float dd = g_dinv[dst];
            float4 v = *(const float4*)&g_xs[src * F + part * 4];
            float* o = &out[dst * F + part * 4];
            atomicAdd(o + 0, v.x * dd);
            atomicAdd(o + 1, v.y * dd);
            atomicAdd(o + 2, v.z * dd);
            atomicAdd(o + 3, v.w * dd);
        }
    }
}

__global__ void k_epilogue(float* __restrict__ out,
                           const float* __restrict__ b,
                           const float* __restrict__ a) {
    int i = blockIdx.x * blockDim.x + threadIdx.x;   // one float4 per thread
    if (i < N_NODES * F / 4) {
        float4 v = ((float4*)out)[i];
        int c = (i & 15) * 4;       // column of first element (64 cols / 4)
        float4 bb = *(const float4*)&b[c];
        float slope = a[0];
        v.x += bb.x; v.y += bb.y; v.z += bb.z; v.w += bb.w;
        v.x = (v.x >= 0.0f) ? v.x : slope * v.x;
        v.y = (v.y >= 0.0f) ? v.y : slope * v.y;
        v.z = (v.z >= 0.0f) ? v.z : slope * v.z;
        v.w = (v.w >= 0.0f) ? v.w : slope * v.w;
        ((float4*)out)[i] = v;
    }
}

extern "C" void kernel_launch(void* const* d_in, const int* in_sizes, int n_in,
                              void* d_out, int out_size) {
    const float* x  = (const float*)d_in[0];
    const int*   ei = (const int*)d_in[1];   // edge_index [2, E] (int32 — JAX x64 disabled)
    const float* W  = (const float*)d_in[2];
    const float* b  = (const float*)d_in[3];
    const float* a  = (const float*)d_in[4];
    float* out = (float*)d_out;

    k_deg_init<<<(N_NODES + 255) / 256, 256>>>();
    k_deg_scatter<<<(N_EDGES / 4 + 255) / 256, 256>>>(ei);
    k_dinv<<<(N_NODES + 255) / 256, 256>>>();
    k_gemm<<<(N_NODES + 3) / 4, 256>>>(x, W, out);
    k_scatter<<<((long long)N_EDGES * 16 + 255) / 256, 256>>>(ei, out);
    k_epilogue<<<(N_NODES * F / 4 + 255) / 256, 256>>>(out, b, a);
}

// round 5
// speedup vs baseline: 1.7978x; 1.7978x over previous
#include <cuda_runtime.h>

#define N_NODES 100000
#define N_EDGES 1600000
#define F 64

// Scratch (device globals — no allocation allowed in kernel_launch)
__device__ float g_deg[N_NODES];
__device__ float g_dinv[N_NODES];
__device__ float g_xs[N_NODES * F];   // (x @ W) * dinv[row]

__global__ void k_deg_init() {
    int i = blockIdx.x * blockDim.x + threadIdx.x;
    if (i < N_NODES) g_deg[i] = 1.0f;   // self-loop contributes 1
}

// 4 edges per thread via int4 load of dst indices (N_EDGES % 4 == 0)
__global__ void k_deg_scatter(const int* __restrict__ ei) {
    int t = blockIdx.x * blockDim.x + threadIdx.x;
    if (t < N_EDGES / 4) {
        int4 d4 = ((const int4*)(ei + N_EDGES))[t];
        if ((unsigned)d4.x < N_NODES) atomicAdd(&g_deg[d4.x], 1.0f);
        if ((unsigned)d4.y < N_NODES) atomicAdd(&g_deg[d4.y], 1.0f);
        if ((unsigned)d4.z < N_NODES) atomicAdd(&g_deg[d4.z], 1.0f);
        if ((unsigned)d4.w < N_NODES) atomicAdd(&g_deg[d4.w], 1.0f);
    }
}

__global__ void k_dinv() {
    int i = blockIdx.x * blockDim.x + threadIdx.x;
    if (i < N_NODES) g_dinv[i] = rsqrtf(g_deg[i]);  // deg >= 1 always
}

// GEMM v2: W column in registers (no W LDS), x rows via broadcast LDS.128.
// 256 threads = 4 row-groups x 64 cols; each thread does 8 rows.
// 3125 blocks x 32 rows = 100000 exactly.
#define ROWS_BLK 32
__global__ void __launch_bounds__(256) k_gemm(const float* __restrict__ x,
                                              const float* __restrict__ W,
                                              float* __restrict__ out) {
    __shared__ float4 xsh[ROWS_BLK * 16];   // 32 rows x 64 floats
    int tid = threadIdx.x;
    int c  = tid & 63;
    int rg = tid >> 6;                      // 0..3

    float Wc[F];                            // W[:, c] in registers
    #pragma unroll
    for (int k = 0; k < F; k++) Wc[k] = W[k * F + c];

    int row0 = blockIdx.x * ROWS_BLK;
    const float4* x4 = (const float4*)(x + row0 * F);
    #pragma unroll
    for (int i = tid; i < ROWS_BLK * 16; i += 256) xsh[i] = x4[i];
    __syncthreads();

    #pragma unroll
    for (int rr = 0; rr < 8; rr++) {
        int r = rg * 8 + rr;
        float acc = 0.0f;
        #pragma unroll
        for (int k0 = 0; k0 < 16; k0++) {
            float4 xv = xsh[r * 16 + k0];   // broadcast within warp
            acc += xv.x * Wc[4 * k0 + 0];
            acc += xv.y * Wc[4 * k0 + 1];
            acc += xv.z * Wc[4 * k0 + 2];
            acc += xv.w * Wc[4 * k0 + 3];
        }
        int row = row0 + r;
        float di = g_dinv[row];
        float v = acc * di;
        g_xs[row * F + c] = v;
        out[row * F + c]  = v * di;         // self-loop message
    }
}

// Scatter v2: 4 threads per edge, 16 floats each, vector REDs (red.global.add.v4.f32).
__global__ void k_scatter(const int* __restrict__ ei,
                          float* __restrict__ out) {
    int t = blockIdx.x * blockDim.x + threadIdx.x;
    int e = t >> 2;
    int part = t & 3;
    if (e < N_EDGES) {
        unsigned src = (unsigned)__ldg(ei + e);
        unsigned dst = (unsigned)__ldg(ei + N_EDGES + e);
        if (src < N_NODES && dst < N_NODES) {
            float dd = g_dinv[dst];
            const float4* xs4 = (const float4*)&g_xs[src * F] + part * 4;
            float* o = &out[dst * F + part * 16];
            float4 v0 = xs4[0];
            float4 v1 = xs4[1];
            float4 v2 = xs4[2];
            float4 v3 = xs4[3];
            asm volatile("red.global.add.v4.f32 [%0], {%1,%2,%3,%4};" ::
                "l"(o + 0),  "f"(v0.x * dd), "f"(v0.y * dd), "f"(v0.z * dd), "f"(v0.w * dd) : "memory");
            asm volatile("red.global.add.v4.f32 [%0], {%1,%2,%3,%4};" ::
                "l"(o + 4),  "f"(v1.x * dd), "f"(v1.y * dd), "f"(v1.z * dd), "f"(v1.w * dd) : "memory");
            asm volatile("red.global.add.v4.f32 [%0], {%1,%2,%3,%4};" ::
                "l"(o + 8),  "f"(v2.x * dd), "f"(v2.y * dd), "f"(v2.z * dd), "f"(v2.w * dd) : "memory");
            asm volatile("red.global.add.v4.f32 [%0], {%1,%2,%3,%4};" ::
                "l"(o + 12), "f"(v3.x * dd), "f"(v3.y * dd), "f"(v3.z * dd), "f"(v3.w * dd) : "memory");
        }
    }
}

__global__ void k_epilogue(float* __restrict__ out,
                           const float* __restrict__ b,
                           const float* __restrict__ a) {
    int i = blockIdx.x * blockDim.x + threadIdx.x;   // one float4 per thread
    if (i < N_NODES * F / 4) {
        float4 v = ((float4*)out)[i];
        int c = (i & 15) * 4;
        float4 bb = *(const float4*)&b[c];
        float slope = a[0];
        v.x += bb.x; v.y += bb.y; v.z += bb.z; v.w += bb.w;
        v.x = (v.x >= 0.0f) ? v.x : slope * v.x;
        v.y = (v.y >= 0.0f) ? v.y : slope * v.y;
        v.z = (v.z >= 0.0f) ? v.z : slope * v.z;
        v.w = (v.w >= 0.0f) ? v.w : slope * v.w;
        ((float4*)out)[i] = v;
    }
}

extern "C" void kernel_launch(void* const* d_in, const int* in_sizes, int n_in,
                              void* d_out, int out_size) {
    const float* x  = (const float*)d_in[0];
    const int*   ei = (const int*)d_in[1];   // edge_index [2, E] (int32)
    const float* W  = (const float*)d_in[2];
    const float* b  = (const float*)d_in[3];
    const float* a  = (const float*)d_in[4];
    float* out = (float*)d_out;

    k_deg_init<<<(N_NODES + 255) / 256, 256>>>();
    k_deg_scatter<<<(N_EDGES / 4 + 255) / 256, 256>>>(ei);
    k_dinv<<<(N_NODES + 255) / 256, 256>>>();
    k_gemm<<<N_NODES / ROWS_BLK, 256>>>(x, W, out);
    k_scatter<<<(N_EDGES * 4 + 255) / 256, 256>>>(ei, out);
    k_epilogue<<<(N_NODES * F / 4 + 255) / 256, 256>>>(out, b, a);
}

// round 6
// speedup vs baseline: 2.7986x; 1.5567x over previous
#include <cuda_runtime.h>

#define N_NODES 100000
#define N_EDGES 1600000
#define F 64
#define SCAN_BLK 512
#define NB ((N_NODES + SCAN_BLK - 1) / SCAN_BLK)   // 196

// Scratch (device globals — no allocation in kernel_launch)
__device__ int   g_cnt[N_NODES];
__device__ int   g_scan[N_NODES];
__device__ int   g_bsum[NB];
__device__ int   g_bsumscan[NB];
__device__ int   g_rowptr[N_NODES + 1];
__device__ int   g_cursor[N_NODES];
__device__ int   g_srt[N_EDGES];        // src indices bucketed by dst
__device__ float g_dinv[N_NODES];
__device__ float g_xs[N_NODES * F];     // (x @ W) * dinv[row]

__global__ void k_zero_cnt() {
    int i = blockIdx.x * blockDim.x + threadIdx.x;
    if (i < N_NODES) g_cnt[i] = 0;
}

// count in-degree (real edges only); 4 edges/thread via int4
__global__ void k_count(const int* __restrict__ ei) {
    int t = blockIdx.x * blockDim.x + threadIdx.x;
    if (t < N_EDGES / 4) {
        int4 d4 = ((const int4*)(ei + N_EDGES))[t];
        if ((unsigned)d4.x < N_NODES) atomicAdd(&g_cnt[d4.x], 1);
        if ((unsigned)d4.y < N_NODES) atomicAdd(&g_cnt[d4.y], 1);
        if ((unsigned)d4.z < N_NODES) atomicAdd(&g_cnt[d4.z], 1);
        if ((unsigned)d4.w < N_NODES) atomicAdd(&g_cnt[d4.w], 1);
    }
}

// per-block inclusive scan of g_cnt
__global__ void __launch_bounds__(SCAN_BLK) k_scan_block() {
    __shared__ int s[SCAN_BLK];
    int t = threadIdx.x;
    int i = blockIdx.x * SCAN_BLK + t;
    s[t] = (i < N_NODES) ? g_cnt[i] : 0;
    __syncthreads();
    #pragma unroll
    for (int off = 1; off < SCAN_BLK; off <<= 1) {
        int v = (t >= off) ? s[t - off] : 0;
        __syncthreads();
        s[t] += v;
        __syncthreads();
    }
    if (i < N_NODES) g_scan[i] = s[t];
    if (t == SCAN_BLK - 1) g_bsum[blockIdx.x] = s[t];
}

// single-block inclusive scan of block sums (NB <= 256)
__global__ void __launch_bounds__(256) k_scan_top() {
    __shared__ int s[256];
    int t = threadIdx.x;
    s[t] = (t < NB) ? g_bsum[t] : 0;
    __syncthreads();
    #pragma unroll
    for (int off = 1; off < 256; off <<= 1) {
        int v = (t >= off) ? s[t - off] : 0;
        __syncthreads();
        s[t] += v;
        __syncthreads();
    }
    if (t < NB) g_bsumscan[t] = s[t];
}

// rowptr/cursor/dinv from scans
__global__ void k_finalize() {
    int i = blockIdx.x * blockDim.x + threadIdx.x;
    if (i < N_NODES) {
        int b = i / SCAN_BLK;
        int incl = g_scan[i] + (b > 0 ? g_bsumscan[b - 1] : 0);
        int cnt = g_cnt[i];
        int excl = incl - cnt;
        g_rowptr[i] = excl;
        g_cursor[i] = excl;
        if (i == N_NODES - 1) g_rowptr[N_NODES] = incl;
        g_dinv[i] = rsqrtf((float)(cnt + 1));     // +1 self-loop
    }
}

// bucket src indices by dst
__global__ void k_fill(const int* __restrict__ ei) {
    int e = blockIdx.x * blockDim.x + threadIdx.x;
    if (e < N_EDGES) {
        unsigned src = (unsigned)__ldg(ei + e);
        unsigned dst = (unsigned)__ldg(ei + N_EDGES + e);
        if (src < N_NODES && dst < N_NODES) {
            int pos = atomicAdd(&g_cursor[dst], 1);
            g_srt[pos] = (int)src;
        }
    }
}

// GEMM: W column in registers, x rows via broadcast LDS.128; xs = (x@W)*dinv[row]
#define ROWS_BLK 32
__global__ void __launch_bounds__(256) k_gemm(const float* __restrict__ x,
                                              const float* __restrict__ W) {
    __shared__ float4 xsh[ROWS_BLK * 16];
    int tid = threadIdx.x;
    int c  = tid & 63;
    int rg = tid >> 6;

    float Wc[F];
    #pragma unroll
    for (int k = 0; k < F; k++) Wc[k] = W[k * F + c];

    int row0 = blockIdx.x * ROWS_BLK;
    const float4* x4 = (const float4*)(x + row0 * F);
    #pragma unroll
    for (int i = tid; i < ROWS_BLK * 16; i += 256) xsh[i] = x4[i];
    __syncthreads();

    #pragma unroll
    for (int rr = 0; rr < 8; rr++) {
        int r = rg * 8 + rr;
        float acc = 0.0f;
        #pragma unroll
        for (int k0 = 0; k0 < 16; k0++) {
            float4 xv = xsh[r * 16 + k0];
            acc += xv.x * Wc[4 * k0 + 0];
            acc += xv.y * Wc[4 * k0 + 1];
            acc += xv.z * Wc[4 * k0 + 2];
            acc += xv.w * Wc[4 * k0 + 3];
        }
        int row = row0 + r;
        g_xs[row * F + c] = acc * g_dinv[row];
    }
}

// One warp per dst node: register accumulation of in-edge messages,
// fused self-loop + dinv[dst] + bias + PReLU. No atomics on out.
__global__ void __launch_bounds__(256) k_accum(float* __restrict__ out,
                                               const float* __restrict__ b,
                                               const float* __restrict__ a) {
    int w = (blockIdx.x * blockDim.x + threadIdx.x) >> 5;
    int lane = threadIdx.x & 31;
    if (w >= N_NODES) return;
    int d = w;
    int beg = g_rowptr[d];
    int end = g_rowptr[d + 1];

    const float2* xs2 = (const float2*)g_xs;
    int lp = lane;                             // float2 slot within row (32 per row)
    float2 acc0 = xs2[d * 32 + lp];            // self-loop term (xs[d])
    float2 acc1 = make_float2(0.0f, 0.0f);

    int i = beg;
    while (i < end) {
        int m = end - i;
        if (m > 32) m = 32;
        int my = (lane < m) ? g_srt[i + lane] : 0;
        for (int j = 0; j < m; j++) {
            int s = __shfl_sync(0xffffffffu, my, j);
            float2 v = xs2[s * 32 + lp];
            if (j & 1) { acc1.x += v.x; acc1.y += v.y; }
            else       { acc0.x += v.x; acc0.y += v.y; }
        }
        i += m;
    }

    float di = g_dinv[d];
    float2 bb = ((const float2*)b)[lp];
    float slope = a[0];
    float ox = (acc0.x + acc1.x) * di + bb.x;
    float oy = (acc0.y + acc1.y) * di + bb.y;
    ox = (ox >= 0.0f) ? ox : slope * ox;
    oy = (oy >= 0.0f) ? oy : slope * oy;
    ((float2*)out)[d * 32 + lp] = make_float2(ox, oy);
}

extern "C" void kernel_launch(void* const* d_in, const int* in_sizes, int n_in,
                              void* d_out, int out_size) {
    const float* x  = (const float*)d_in[0];
    const int*   ei = (const int*)d_in[1];   // edge_index [2, E] (int32)
    const float* W  = (const float*)d_in[2];
    const float* b  = (const float*)d_in[3];
    const float* a  = (const float*)d_in[4];
    float* out = (float*)d_out;

    k_zero_cnt<<<(N_NODES + 255) / 256, 256>>>();
    k_count<<<(N_EDGES / 4 + 255) / 256, 256>>>(ei);
    k_scan_block<<<NB, SCAN_BLK>>>();
    k_scan_top<<<1, 256>>>();
    k_finalize<<<(N_NODES + 255) / 256, 256>>>();
    k_fill<<<(N_EDGES + 255) / 256, 256>>>(ei);
    k_gemm<<<N_NODES / ROWS_BLK, 256>>>(x, W);
    k_accum<<<(N_NODES * 32 + 255) / 256, 256>>>(out, b, a);
}